// round 6
// baseline (speedup 1.0000x reference)
#include <cuda_runtime.h>
#include <cstdint>

#define S_LEN 2048
#define D_MODEL 2048
#define NB 2
#define NH 16
#define DHD 128
#define M_ROWS (NB * S_LEN) /* 4096 */
#define KDIM D_MODEL

// ---------------- scratch (static __device__, allocation-guard safe) -------
__device__ float g_q[(size_t)NB * NH * S_LEN * DHD];   // [b][h][s][d]
__device__ float g_k[(size_t)NB * NH * S_LEN * DHD];
__device__ float g_v[(size_t)NB * NH * S_LEN * DHD];
__device__ float g_ao[(size_t)M_ROWS * D_MODEL];       // [b*s][h*128+d]

// ---------------- tf32 helpers --------------------------------------------
__device__ __forceinline__ uint32_t f2tf(float x) {
    uint32_t r;
    asm("cvt.rna.tf32.f32 %0, %1;" : "=r"(r) : "f"(x));
    return r;
}

__device__ __forceinline__ void mma8(float c[4], const uint32_t a[4], const uint32_t b[2]) {
    asm volatile(
        "mma.sync.aligned.m16n8k8.row.col.f32.tf32.tf32.f32 "
        "{%0,%1,%2,%3}, {%4,%5,%6,%7}, {%8,%9}, {%0,%1,%2,%3};"
        : "+f"(c[0]), "+f"(c[1]), "+f"(c[2]), "+f"(c[3])
        : "r"(a[0]), "r"(a[1]), "r"(a[2]), "r"(a[3]), "r"(b[0]), "r"(b[1]));
}

// ---------------- GEMM: C[M,N] = A[M,K] @ W[N,K]^T -------------------------
// block tile 128x128, BK=32, 256 threads (8 warps, 2x4), warp tile 64x32.
// smem holds tf32 bits in PERMUTED layout: col' = (c&3)*8 + (c>>2), stride 36
// (conflict-free LDS.128 fragment loads). Double-buffered; global prefetch
// staged in registers; one __syncthreads per K-chunk.
// mode 0: RoPE -> g_q   mode 1: RoPE -> g_k   mode 2: plain -> g_v
// mode 3 (is_final): A = g_ao, plain row-major -> Oout (d_out)
#define GEMM_SMEM (2 * 2 * 128 * 36 * 4) /* 73728 bytes */

__global__ __launch_bounds__(256) void gemm_tf32_kernel(
    const float* __restrict__ A_in,
    const float* __restrict__ W0, const float* __restrict__ W1,
    const float* __restrict__ W2,
    float* __restrict__ Oout,
    const float* __restrict__ fc, const float* __restrict__ fs,
    int is_final)
{
    extern __shared__ uint32_t sm[];  // [buf][As 128*36 | Bs 128*36]

    const int mode = is_final ? 3 : (int)blockIdx.z;
    const float* A = is_final ? g_ao : A_in;
    const float* Wm = (mode == 1) ? W1 : (mode == 2) ? W2 : W0;

    const int tid  = threadIdx.x;
    const int warp = tid >> 5, lane = tid & 31;
    const int wm = warp >> 2, wn = warp & 3;     // 2 x 4 warp grid
    const int g  = lane >> 2, tg = lane & 3;

    const int bm = blockIdx.y, bn = blockIdx.x;

    float acc[4][4][4];
#pragma unroll
    for (int mi = 0; mi < 4; mi++)
#pragma unroll
        for (int ni = 0; ni < 4; ni++)
#pragma unroll
            for (int j = 0; j < 4; j++) acc[mi][ni][j] = 0.f;

    const float* Ablk = A  + (size_t)(bm * 128) * KDIM;
    const float* Bblk = Wm + (size_t)(bn * 128) * KDIM;

    // staging registers for next chunk
    float4 sa[4], sb[4];

    // ---- prefetch chunk 0 ----
#pragma unroll
    for (int i = 0; i < 4; i++) {
        int li = tid + i * 256;
        int r  = li >> 3;
        int c4 = (li & 7) << 2;
        sa[i] = *(const float4*)(Ablk + (size_t)r * KDIM + c4);
        sb[i] = *(const float4*)(Bblk + (size_t)r * KDIM + c4);
    }
    // ---- store chunk 0 into buffer 0 (cvt + permute) ----
    {
        uint32_t* As = sm;
        uint32_t* Bs = sm + 128 * 36;
#pragma unroll
        for (int i = 0; i < 4; i++) {
            int li = tid + i * 256;
            int r  = li >> 3;
            int j  = li & 7;
            As[r * 36 + j]      = f2tf(sa[i].x);
            As[r * 36 + 8 + j]  = f2tf(sa[i].y);
            As[r * 36 + 16 + j] = f2tf(sa[i].z);
            As[r * 36 + 24 + j] = f2tf(sa[i].w);
            Bs[r * 36 + j]      = f2tf(sb[i].x);
            Bs[r * 36 + 8 + j]  = f2tf(sb[i].y);
            Bs[r * 36 + 16 + j] = f2tf(sb[i].z);
            Bs[r * 36 + 24 + j] = f2tf(sb[i].w);
        }
    }

    const int nk = KDIM / 32;
    for (int kc = 0; kc < nk; kc++) {
        __syncthreads();

        // prefetch next chunk to registers (latency hides under MMA below)
        if (kc + 1 < nk) {
            int k0 = (kc + 1) * 32;
#pragma unroll
            for (int i = 0; i < 4; i++) {
                int li = tid + i * 256;
                int r  = li >> 3;
                int c4 = (li & 7) << 2;
                sa[i] = *(const float4*)(Ablk + (size_t)r * KDIM + k0 + c4);
                sb[i] = *(const float4*)(Bblk + (size_t)r * KDIM + k0 + c4);
            }
        }

        // ---- compute chunk kc from buffer kc&1 ----
        const uint32_t* As = sm + (kc & 1) * (2 * 128 * 36);
        const uint32_t* Bs = As + 128 * 36;

        uint32_t bfr[4][8];
#pragma unroll
        for (int ni = 0; ni < 4; ni++) {
            int n0 = wn * 32 + ni * 8 + g;
            uint4 t0 = *(const uint4*)(Bs + n0 * 36 + tg * 8);
            uint4 t1 = *(const uint4*)(Bs + n0 * 36 + tg * 8 + 4);
            bfr[ni][0] = t0.x; bfr[ni][1] = t0.y; bfr[ni][2] = t0.z; bfr[ni][3] = t0.w;
            bfr[ni][4] = t1.x; bfr[ni][5] = t1.y; bfr[ni][6] = t1.z; bfr[ni][7] = t1.w;
        }
#pragma unroll
        for (int mi = 0; mi < 4; mi++) {
            int r0 = wm * 64 + mi * 16 + g;
            uint4 a0 = *(const uint4*)(As + r0 * 36 + tg * 8);
            uint4 a1 = *(const uint4*)(As + r0 * 36 + tg * 8 + 4);
            uint4 a2 = *(const uint4*)(As + (r0 + 8) * 36 + tg * 8);
            uint4 a3 = *(const uint4*)(As + (r0 + 8) * 36 + tg * 8 + 4);
            uint32_t ar0[8] = {a0.x, a0.y, a0.z, a0.w, a1.x, a1.y, a1.z, a1.w};
            uint32_t ar8[8] = {a2.x, a2.y, a2.z, a2.w, a3.x, a3.y, a3.z, a3.w};
#pragma unroll
            for (int ni = 0; ni < 4; ni++) {
#pragma unroll
                for (int kk = 0; kk < 4; kk++) {
                    uint32_t ua[4] = {ar0[2 * kk], ar8[2 * kk],
                                      ar0[2 * kk + 1], ar8[2 * kk + 1]};
                    uint32_t ub[2] = {bfr[ni][2 * kk], bfr[ni][2 * kk + 1]};
                    mma8(acc[mi][ni], ua, ub);
                }
            }
        }

        // ---- store next chunk into other buffer ----
        if (kc + 1 < nk) {
            uint32_t* Asn = sm + ((kc + 1) & 1) * (2 * 128 * 36);
            uint32_t* Bsn = Asn + 128 * 36;
#pragma unroll
            for (int i = 0; i < 4; i++) {
                int li = tid + i * 256;
                int r  = li >> 3;
                int j  = li & 7;
                Asn[r * 36 + j]      = f2tf(sa[i].x);
                Asn[r * 36 + 8 + j]  = f2tf(sa[i].y);
                Asn[r * 36 + 16 + j] = f2tf(sa[i].z);
                Asn[r * 36 + 24 + j] = f2tf(sa[i].w);
                Bsn[r * 36 + j]      = f2tf(sb[i].x);
                Bsn[r * 36 + 8 + j]  = f2tf(sb[i].y);
                Bsn[r * 36 + 16 + j] = f2tf(sb[i].z);
                Bsn[r * 36 + 24 + j] = f2tf(sb[i].w);
            }
        }
    }

    // ---- epilogue ----
#pragma unroll
    for (int mi = 0; mi < 4; mi++) {
#pragma unroll
        for (int ni = 0; ni < 4; ni++) {
            int m0 = bm * 128 + wm * 64 + mi * 16 + g;
            int n0 = bn * 128 + wn * 32 + ni * 8 + tg * 2;
#pragma unroll
            for (int h2 = 0; h2 < 2; h2++) {
                int m = m0 + h2 * 8;
                float e = acc[mi][ni][h2 * 2];
                float o = acc[mi][ni][h2 * 2 + 1];
                if (mode == 3) {
                    *(float2*)(Oout + (size_t)m * D_MODEL + n0) = make_float2(e, o);
                } else {
                    int b = m >> 11, s = m & 2047;
                    int hh = n0 >> 7, d = n0 & 127;
                    if (mode != 2) {  // RoPE for Q, K
                        float c  = fc[s * 64 + (d >> 1)];
                        float sn = fs[s * 64 + (d >> 1)];
                        float e2 = e * c - o * sn;
                        float o2 = e * sn + o * c;
                        e = e2; o = o2;
                    }
                    size_t idx = ((size_t)(b * NH + hh) * S_LEN + s) * DHD + d;
                    float* dst = (mode == 0) ? g_q : (mode == 1) ? g_k : g_v;
                    *(float2*)(dst + idx) = make_float2(e, o);
                }
            }
        }
    }
}

// ---------------- Flash attention ------------------------------------------
// Block: (qb, bh). 256 threads, 8 warps x 16 q-rows. BQ=128, BKV=64.
// K/V/P held in smem as PRE-CONVERTED tf32 bits (cvt once at store time;
// removes ~600 CVT issue slots per thread per KV tile vs Round 2).
#define KPAD 132
#define PPAD 68
#define ATT_SMEM ((2 * 64 * KPAD + 8 * 16 * PPAD) * 4) /* 102400 bytes */

__global__ __launch_bounds__(256) void attn_flash_kernel(float* __restrict__ out)
{
    extern __shared__ uint32_t smem_raw[];
    uint32_t (*Ks)[KPAD] = reinterpret_cast<uint32_t(*)[KPAD]>(smem_raw);
    uint32_t (*Vs)[KPAD] = reinterpret_cast<uint32_t(*)[KPAD]>(smem_raw + 64 * KPAD);
    uint32_t (*Ps)[PPAD] = reinterpret_cast<uint32_t(*)[PPAD]>(smem_raw + 2 * 64 * KPAD);

    const int bh = blockIdx.y;       // b*16 + h
    const int qb = blockIdx.x;       // q tile of 128
    const int tid = threadIdx.x;
    const int warp = tid >> 5, lane = tid & 31;
    const int g = lane >> 2, tg = lane & 3;
    const int r0 = qb * 128 + warp * 16 + g;  // global q row (second: +8)

    const float* qbase = g_q + (size_t)bh * S_LEN * DHD;
    const float* kbase = g_k + (size_t)bh * S_LEN * DHD;
    const float* vbase = g_v + (size_t)bh * S_LEN * DHD;

    const float scale = 0.08838834764831845f;  // 1/sqrt(128)

    // Q fragments for the whole DH=128 (16 k-steps of 8), scale folded in.
    uint32_t qf[16][4];
#pragma unroll
    for (int kk = 0; kk < 16; kk++) {
        int c = kk * 8 + tg;
        qf[kk][0] = f2tf(qbase[(size_t)r0 * DHD + c] * scale);
        qf[kk][1] = f2tf(qbase[(size_t)(r0 + 8) * DHD + c] * scale);
        qf[kk][2] = f2tf(qbase[(size_t)r0 * DHD + c + 4] * scale);
        qf[kk][3] = f2tf(qbase[(size_t)(r0 + 8) * DHD + c + 4] * scale);
    }

    float oacc[16][4];
#pragma unroll
    for (int ni = 0; ni < 16; ni++)
#pragma unroll
        for (int j = 0; j < 4; j++) oacc[ni][j] = 0.f;

    float m0v = -1e30f, m1v = -1e30f, l0 = 0.f, l1 = 0.f;

    const int nkv = 2 * (qb + 1);  // 64-wide kv tiles covering the causal range
    for (int t = 0; t < nkv; t++) {
        const int kv0 = t * 64;
        __syncthreads();
        // cooperative load of K,V tiles (64 x 128 each), tf32-convert at store
#pragma unroll
        for (int i = 0; i < 8; i++) {
            int li = tid + i * 256;          // 0..2047 float4 slots
            int r  = li >> 5;                // 32 float4 per row
            int c4 = (li & 31) << 2;
            float4 kv = *(const float4*)(kbase + (size_t)(kv0 + r) * DHD + c4);
            uint4 ku; ku.x = f2tf(kv.x); ku.y = f2tf(kv.y);
            ku.z = f2tf(kv.z); ku.w = f2tf(kv.w);
            *(uint4*)(&Ks[r][c4]) = ku;
            float4 vv = *(const float4*)(vbase + (size_t)(kv0 + r) * DHD + c4);
            uint4 vu; vu.x = f2tf(vv.x); vu.y = f2tf(vv.y);
            vu.z = f2tf(vv.z); vu.w = f2tf(vv.w);
            *(uint4*)(&Vs[r][c4]) = vu;
        }
        __syncthreads();

        if (kv0 <= qb * 128 + warp * 16 + 15) {   // warp has unmasked work
            // ---- scores: S = Q K^T (already scaled) ----
            float s[8][4];
#pragma unroll
            for (int ni = 0; ni < 8; ni++)
#pragma unroll
                for (int j = 0; j < 4; j++) s[ni][j] = 0.f;

#pragma unroll
            for (int kk = 0; kk < 16; kk++) {
                const int kc = kk * 8 + tg;
#pragma unroll
                for (int ni = 0; ni < 8; ni++) {
                    uint32_t bf[2];
                    bf[0] = Ks[ni * 8 + g][kc];
                    bf[1] = Ks[ni * 8 + g][kc + 4];
                    mma8(s[ni], qf[kk], bf);
                }
            }

            // ---- causal mask + tile max ----
            float mn0 = -1e30f, mn1 = -1e30f;
#pragma unroll
            for (int ni = 0; ni < 8; ni++) {
                int c = kv0 + ni * 8 + tg * 2;
                if (c > r0)         s[ni][0] = -1e30f;
                if (c + 1 > r0)     s[ni][1] = -1e30f;
                if (c > r0 + 8)     s[ni][2] = -1e30f;
                if (c + 1 > r0 + 8) s[ni][3] = -1e30f;
                mn0 = fmaxf(mn0, fmaxf(s[ni][0], s[ni][1]));
                mn1 = fmaxf(mn1, fmaxf(s[ni][2], s[ni][3]));
            }
            mn0 = fmaxf(mn0, __shfl_xor_sync(0xffffffffu, mn0, 1));
            mn0 = fmaxf(mn0, __shfl_xor_sync(0xffffffffu, mn0, 2));
            mn1 = fmaxf(mn1, __shfl_xor_sync(0xffffffffu, mn1, 1));
            mn1 = fmaxf(mn1, __shfl_xor_sync(0xffffffffu, mn1, 2));

            float mt0 = fmaxf(m0v, mn0), mt1 = fmaxf(m1v, mn1);
            float a0 = __expf(m0v - mt0), a1 = __expf(m1v - mt1);
            m0v = mt0; m1v = mt1;

            // ---- exp + tf32 P to per-warp smem ----
            float rs0 = 0.f, rs1 = 0.f;
#pragma unroll
            for (int ni = 0; ni < 8; ni++) {
                float p0 = __expf(s[ni][0] - mt0);
                float p1 = __expf(s[ni][1] - mt0);
                float p2 = __expf(s[ni][2] - mt1);
                float p3 = __expf(s[ni][3] - mt1);
                rs0 += p0 + p1;
                rs1 += p2 + p3;
                int cc = ni * 8 + tg * 2;
                uint2 u01; u01.x = f2tf(p0); u01.y = f2tf(p1);
                uint2 u23; u23.x = f2tf(p2); u23.y = f2tf(p3);
                *(uint2*)(&Ps[(warp << 4) + g][cc])     = u01;
                *(uint2*)(&Ps[(warp << 4) + g + 8][cc]) = u23;
            }
            rs0 += __shfl_xor_sync(0xffffffffu, rs0, 1);
            rs0 += __shfl_xor_sync(0xffffffffu, rs0, 2);
            rs1 += __shfl_xor_sync(0xffffffffu, rs1, 1);
            rs1 += __shfl_xor_sync(0xffffffffu, rs1, 2);
            l0 = l0 * a0 + rs0;
            l1 = l1 * a1 + rs1;

            // rescale running output
#pragma unroll
            for (int ni = 0; ni < 16; ni++) {
                oacc[ni][0] *= a0; oacc[ni][1] *= a0;
                oacc[ni][2] *= a1; oacc[ni][3] *= a1;
            }
            __syncwarp();

            // ---- O += P @ V ----
#pragma unroll
            for (int kk2 = 0; kk2 < 8; kk2++) {
                const int kc = kk2 * 8 + tg;
                uint32_t af[4];
                af[0] = Ps[(warp << 4) + g][kc];
                af[1] = Ps[(warp << 4) + g + 8][kc];
                af[2] = Ps[(warp << 4) + g][kc + 4];
                af[3] = Ps[(warp << 4) + g + 8][kc + 4];
#pragma unroll
                for (int ni2 = 0; ni2 < 16; ni2++) {
                    uint32_t bf[2];
                    bf[0] = Vs[kc][ni2 * 8 + g];
                    bf[1] = Vs[kc + 4][ni2 * 8 + g];
                    mma8(oacc[ni2], af, bf);
                }
            }
        }
    }

    // ---- epilogue: divide by l, write [b][s][h*128+d] ----
    const int b = bh >> 4, h = bh & 15;
    const float inv0 = 1.f / l0, inv1 = 1.f / l1;
#pragma unroll
    for (int ni2 = 0; ni2 < 16; ni2++) {
        int d = ni2 * 8 + tg * 2;
        size_t i0 = ((size_t)b * S_LEN + r0) * D_MODEL + h * DHD + d;
        size_t i1 = ((size_t)b * S_LEN + r0 + 8) * D_MODEL + h * DHD + d;
        *(float2*)(out + i0) = make_float2(oacc[ni2][0] * inv0, oacc[ni2][1] * inv0);
        *(float2*)(out + i1) = make_float2(oacc[ni2][2] * inv1, oacc[ni2][3] * inv1);
    }
}

// ---------------- launch ----------------------------------------------------
extern "C" void kernel_launch(void* const* d_in, const int* in_sizes, int n_in,
                              void* d_out, int out_size)
{
    (void)in_sizes; (void)n_in; (void)out_size;
    const float* x  = (const float*)d_in[0];
    const float* fc = (const float*)d_in[1];
    const float* fs = (const float*)d_in[2];
    // d_in[3] = mask (causal, implemented analytically)
    const float* wq = (const float*)d_in[4];
    const float* wk = (const float*)d_in[5];
    const float* wv = (const float*)d_in[6];
    const float* wo = (const float*)d_in[7];
    float* out = (float*)d_out;

    dim3 blk(256);

    cudaFuncSetAttribute(gemm_tf32_kernel,
                         cudaFuncAttributeMaxDynamicSharedMemorySize, GEMM_SMEM);
    cudaFuncSetAttribute(attn_flash_kernel,
                         cudaFuncAttributeMaxDynamicSharedMemorySize, ATT_SMEM);

    // 1) fused QKV projections + RoPE
    dim3 g1(D_MODEL / 128, M_ROWS / 128, 3);
    gemm_tf32_kernel<<<g1, blk, GEMM_SMEM>>>(x, wq, wk, wv, out, fc, fs, 0);

    // 2) flash attention -> g_ao
    float* ao_ptr = nullptr;
    cudaGetSymbolAddress((void**)&ao_ptr, g_ao);
    dim3 g2(S_LEN / 128, NB * NH);
    attn_flash_kernel<<<g2, blk, ATT_SMEM>>>(ao_ptr);

    // 3) output projection -> d_out
    dim3 g3(D_MODEL / 128, M_ROWS / 128, 1);
    gemm_tf32_kernel<<<g3, blk, GEMM_SMEM>>>(nullptr, wo, nullptr, nullptr, out, fc, fs, 1);
}

// round 7
// speedup vs baseline: 1.8550x; 1.8550x over previous
#include <cuda_runtime.h>
#include <cuda_fp16.h>
#include <cstdint>

#define S_LEN 2048
#define D_MODEL 2048
#define NB 2
#define NH 16
#define DHD 128
#define M_ROWS 4096

// ---------------- scratch (static __device__, allocation-guard safe) -------
__device__ __align__(16) __half g_xh[(size_t)M_ROWS * D_MODEL];
__device__ __align__(16) __half g_wh[(size_t)4 * D_MODEL * D_MODEL];  // q,k,v,o
__device__ __align__(16) __half g_qh[(size_t)M_ROWS * D_MODEL];       // [b][h][s][d]
__device__ __align__(16) __half g_kh[(size_t)M_ROWS * D_MODEL];
__device__ __align__(16) __half g_vh[(size_t)M_ROWS * D_MODEL];
__device__ __align__(16) __half g_aoh[(size_t)M_ROWS * D_MODEL];      // [b*s][h*128+d]

// ---------------- PTX helpers ----------------------------------------------
__device__ __forceinline__ void ldsm4(uint32_t* r, uint32_t a) {
    asm volatile("ldmatrix.sync.aligned.m8n8.x4.shared.b16 {%0,%1,%2,%3}, [%4];"
                 : "=r"(r[0]), "=r"(r[1]), "=r"(r[2]), "=r"(r[3]) : "r"(a));
}
__device__ __forceinline__ void ldsm4t(uint32_t* r, uint32_t a) {
    asm volatile("ldmatrix.sync.aligned.m8n8.x4.trans.shared.b16 {%0,%1,%2,%3}, [%4];"
                 : "=r"(r[0]), "=r"(r[1]), "=r"(r[2]), "=r"(r[3]) : "r"(a));
}
__device__ __forceinline__ void mma16(float* c, const uint32_t* a, uint32_t b0, uint32_t b1) {
    asm volatile(
        "mma.sync.aligned.m16n8k16.row.col.f32.f16.f16.f32 "
        "{%0,%1,%2,%3}, {%4,%5,%6,%7}, {%8,%9}, {%0,%1,%2,%3};"
        : "+f"(c[0]), "+f"(c[1]), "+f"(c[2]), "+f"(c[3])
        : "r"(a[0]), "r"(a[1]), "r"(a[2]), "r"(a[3]), "r"(b0), "r"(b1));
}
__device__ __forceinline__ void cpa16(uint32_t saddr, const void* gptr) {
    asm volatile("cp.async.cg.shared.global [%0], [%1], 16;" :: "r"(saddr), "l"(gptr));
}
#define CP_COMMIT asm volatile("cp.async.commit_group;" ::: "memory")
#define CP_WAIT0  asm volatile("cp.async.wait_group 0;" ::: "memory")
#define CP_WAIT1  asm volatile("cp.async.wait_group 1;" ::: "memory")

__device__ __forceinline__ uint32_t h2u(float a, float b) {
    __half2 h = __floats2half2_rn(a, b);
    return *reinterpret_cast<uint32_t*>(&h);
}

// ---------------- pre-pass: fp32 -> fp16 ------------------------------------
__global__ __launch_bounds__(256) void cvt_h_kernel(
    const float* __restrict__ x,
    const float* __restrict__ wq, const float* __restrict__ wk,
    const float* __restrict__ wv, const float* __restrict__ wo)
{
    const int z = blockIdx.z;
    const float* src;
    __half* dst;
    int n4;
    if (z == 0)      { src = x;  dst = g_xh; n4 = M_ROWS * D_MODEL / 4; }
    else if (z == 1) { src = wq; dst = g_wh;                                    n4 = D_MODEL * D_MODEL / 4; }
    else if (z == 2) { src = wk; dst = g_wh + (size_t)1 * D_MODEL * D_MODEL;    n4 = D_MODEL * D_MODEL / 4; }
    else if (z == 3) { src = wv; dst = g_wh + (size_t)2 * D_MODEL * D_MODEL;    n4 = D_MODEL * D_MODEL / 4; }
    else             { src = wo; dst = g_wh + (size_t)3 * D_MODEL * D_MODEL;    n4 = D_MODEL * D_MODEL / 4; }

    int idx = blockIdx.x * 256 + threadIdx.x;
    if (idx < n4) {
        float4 v = ((const float4*)src)[idx];
        __half2* d2 = (__half2*)dst + (size_t)idx * 2;
        d2[0] = __floats2half2_rn(v.x, v.y);
        d2[1] = __floats2half2_rn(v.z, v.w);
    }
}

// ---------------- GEMM: C[M,N] = A[M,K] @ W[N,K]^T  (fp16 in, fp32 acc) -----
// Block 128x128, BK=64, 8 warps (2x4), warp tile 64x32.
// cp.async double-buffered, XOR-swizzled smem, ldmatrix fragments.
// mode 0: RoPE -> g_qh   1: RoPE -> g_kh   2: -> g_vh
// mode 3 (is_final): A = g_aoh, fp32 row-major -> Oout (d_out)
#define GEMM_SMEM 65536

__global__ __launch_bounds__(256) void gemm_h_kernel(
    float* __restrict__ Oout,
    const float* __restrict__ fc, const float* __restrict__ fs,
    int is_final)
{
    extern __shared__ __align__(16) char smraw[];
    const uint32_t sb = (uint32_t)__cvta_generic_to_shared(smraw);

    const int mode = is_final ? 3 : (int)blockIdx.z;
    const __half* A = is_final ? g_aoh : g_xh;
    const __half* W = g_wh + (size_t)mode * D_MODEL * D_MODEL;

    const int tid = threadIdx.x;
    const int warp = tid >> 5, lane = tid & 31;
    const int wm = warp >> 2, wn = warp & 3;       // 2 x 4 warp grid
    const int g = lane >> 2, tg = lane & 3;
    const int bm = blockIdx.y, bn = blockIdx.x;

    const __half* Ab = A + (size_t)(bm * 128) * D_MODEL;
    const __half* Bb = W + (size_t)(bn * 128) * D_MODEL;

    float acc[4][4][4];
#pragma unroll
    for (int mi = 0; mi < 4; mi++)
#pragma unroll
        for (int ni = 0; ni < 4; ni++)
#pragma unroll
            for (int j = 0; j < 4; j++) acc[mi][ni][j] = 0.f;

    // async copy of one K-chunk (A 128x64h = 16KB, B 128x64h = 16KB)
    auto docopy = [&](int kc, int buf) {
        const uint32_t s0 = sb + buf * 32768;
#pragma unroll
        for (int i = 0; i < 8; i++) {
            int li = i * 256 + tid;
            if (i < 4) {
                int r = li >> 3, c8 = li & 7;
                cpa16(s0 + r * 128 + ((c8 ^ (r & 7)) << 4),
                      Ab + (size_t)r * D_MODEL + kc * 64 + c8 * 8);
            } else {
                int l2 = li - 1024;
                int r = l2 >> 3, c8 = l2 & 7;
                cpa16(s0 + 16384 + r * 128 + ((c8 ^ (r & 7)) << 4),
                      Bb + (size_t)r * D_MODEL + kc * 64 + c8 * 8);
            }
        }
    };

    const int nk = D_MODEL / 64;   // 32 chunks
    docopy(0, 0);
    CP_COMMIT;

    for (int kc = 0; kc < nk; kc++) {
        if (kc + 1 < nk) { docopy(kc + 1, (kc + 1) & 1); CP_COMMIT; CP_WAIT1; }
        else             { CP_WAIT0; }
        __syncthreads();

        const uint32_t sA = sb + (kc & 1) * 32768;
        const uint32_t sBs = sA + 16384;

#pragma unroll
        for (int kk = 0; kk < 4; kk++) {
            uint32_t bf[4][2];
#pragma unroll
            for (int nip = 0; nip < 2; nip++) {
                int row = wn * 32 + nip * 16 + (lane & 7) + ((lane >> 4) << 3);
                int c8 = kk * 2 + ((lane >> 3) & 1);
                uint32_t r4[4];
                ldsm4(r4, sBs + row * 128 + ((c8 ^ (row & 7)) << 4));
                bf[2 * nip][0] = r4[0]; bf[2 * nip][1] = r4[1];
                bf[2 * nip + 1][0] = r4[2]; bf[2 * nip + 1][1] = r4[3];
            }
#pragma unroll
            for (int mi = 0; mi < 4; mi++) {
                int row = wm * 64 + mi * 16 + (lane & 15);
                int c8 = kk * 2 + (lane >> 4);
                uint32_t a4[4];
                ldsm4(a4, sA + row * 128 + ((c8 ^ (row & 7)) << 4));
#pragma unroll
                for (int ni = 0; ni < 4; ni++)
                    mma16(acc[mi][ni], a4, bf[ni][0], bf[ni][1]);
            }
        }
        __syncthreads();
    }

    // ---- epilogue ----
#pragma unroll
    for (int mi = 0; mi < 4; mi++) {
#pragma unroll
        for (int ni = 0; ni < 4; ni++) {
            int m0 = bm * 128 + wm * 64 + mi * 16 + g;
            int n0 = bn * 128 + wn * 32 + ni * 8 + tg * 2;
#pragma unroll
            for (int h2 = 0; h2 < 2; h2++) {
                int m = m0 + h2 * 8;
                float e = acc[mi][ni][h2 * 2];
                float o = acc[mi][ni][h2 * 2 + 1];
                if (mode == 3) {
                    *(float2*)(Oout + (size_t)m * D_MODEL + n0) = make_float2(e, o);
                } else {
                    int b = m >> 11, s = m & 2047;
                    int hh = n0 >> 7, d = n0 & 127;
                    if (mode != 2) {   // RoPE for Q, K (d even / d+1 pair)
                        float c  = fc[s * 64 + (d >> 1)];
                        float sn = fs[s * 64 + (d >> 1)];
                        float e2 = e * c - o * sn;
                        float o2 = e * sn + o * c;
                        e = e2; o = o2;
                    }
                    __half* dst = (mode == 0) ? g_qh : (mode == 1) ? g_kh : g_vh;
                    size_t idx = ((size_t)(b * NH + hh) * S_LEN + s) * DHD + d;
                    *(__half2*)(dst + idx) = __floats2half2_rn(e, o);
                }
            }
        }
    }
}

// ---------------- Flash attention (fp16 MMA, fp32 softmax/accum) ------------
// Block: (qb, bh). 256 threads, 8 warps x 16 q-rows. BQ=128, BKV=64.
// K/V cp.async double-buffered swizzled smem; K ldmatrix, V ldmatrix.trans.
// P stays in registers: S C-fragment layout == P A-fragment layout at k16.
#define ATT_SMEM 65536

__global__ __launch_bounds__(256) void attn_h_kernel()
{
    extern __shared__ __align__(16) char smraw[];
    const uint32_t sb = (uint32_t)__cvta_generic_to_shared(smraw);

    const int bh = blockIdx.y;     // b*16 + h
    const int qb = blockIdx.x;     // q tile of 128
    const int tid = threadIdx.x;
    const int warp = tid >> 5, lane = tid & 31;
    const int g = lane >> 2, tg = lane & 3;
    const int r0 = qb * 128 + warp * 16 + g;       // q row (+8 for second)

    const __half* kb_p = g_kh + (size_t)bh * S_LEN * DHD;
    const __half* vb_p = g_vh + (size_t)bh * S_LEN * DHD;

    // Q fragments (unscaled; scale applied to scores in fp32)
    uint32_t qf[8][4];
    {
        const __half* q0 = g_qh + ((size_t)bh * S_LEN + r0) * DHD;
        const __half* q1 = q0 + 8 * DHD;
#pragma unroll
        for (int kk = 0; kk < 8; kk++) {
            qf[kk][0] = *(const uint32_t*)(q0 + kk * 16 + tg * 2);
            qf[kk][1] = *(const uint32_t*)(q1 + kk * 16 + tg * 2);
            qf[kk][2] = *(const uint32_t*)(q0 + kk * 16 + 8 + tg * 2);
            qf[kk][3] = *(const uint32_t*)(q1 + kk * 16 + 8 + tg * 2);
        }
    }

    float oacc[16][4];
#pragma unroll
    for (int ni = 0; ni < 16; ni++)
#pragma unroll
        for (int j = 0; j < 4; j++) oacc[ni][j] = 0.f;

    float m0v = -1e30f, m1v = -1e30f, l0 = 0.f, l1 = 0.f;
    const float scale = 0.08838834764831845f;  // 1/sqrt(128)

    // async copy of one KV tile (K 64x128h = 16KB, V 64x128h = 16KB)
    auto docopy = [&](int t, int buf) {
        const uint32_t s0 = sb + buf * 32768;
        const int kv0 = t * 64;
#pragma unroll
        for (int i = 0; i < 8; i++) {
            int li = i * 256 + tid;
            if (i < 4) {
                int r = li >> 4, c16 = li & 15;
                cpa16(s0 + r * 256 + ((c16 ^ (r & 7)) << 4),
                      kb_p + (size_t)(kv0 + r) * DHD + c16 * 8);
            } else {
                int l2 = li - 1024;
                int r = l2 >> 4, c16 = l2 & 15;
                cpa16(s0 + 16384 + r * 256 + ((c16 ^ (r & 7)) << 4),
                      vb_p + (size_t)(kv0 + r) * DHD + c16 * 8);
            }
        }
    };

    const int nkv = 2 * (qb + 1);
    docopy(0, 0);
    CP_COMMIT;

    for (int t = 0; t < nkv; t++) {
        if (t + 1 < nkv) { docopy(t + 1, (t + 1) & 1); CP_COMMIT; CP_WAIT1; }
        else             { CP_WAIT0; }
        __syncthreads();

        const uint32_t Kb = sb + (t & 1) * 32768;
        const uint32_t Vb = Kb + 16384;
        const int kv0 = t * 64;

        if (kv0 <= qb * 128 + warp * 16 + 15) {    // warp has unmasked work
            // ---- S = Q K^T ----
            float s[8][4];
#pragma unroll
            for (int ni = 0; ni < 8; ni++)
#pragma unroll
                for (int j = 0; j < 4; j++) s[ni][j] = 0.f;

#pragma unroll
            for (int kk = 0; kk < 8; kk++) {
#pragma unroll
                for (int nip = 0; nip < 4; nip++) {
                    int row = nip * 16 + (lane & 7) + ((lane >> 4) << 3);
                    int c16 = kk * 2 + ((lane >> 3) & 1);
                    uint32_t r4[4];
                    ldsm4(r4, Kb + row * 256 + ((c16 ^ (row & 7)) << 4));
                    mma16(s[2 * nip],     qf[kk], r4[0], r4[1]);
                    mma16(s[2 * nip + 1], qf[kk], r4[2], r4[3]);
                }
            }

            // ---- scale + causal mask + tile max ----
            float mn0 = -1e30f, mn1 = -1e30f;
#pragma unroll
            for (int ni = 0; ni < 8; ni++) {
                int c = kv0 + ni * 8 + tg * 2;
                s[ni][0] = (c     <= r0)     ? s[ni][0] * scale : -1e30f;
                s[ni][1] = (c + 1 <= r0)     ? s[ni][1] * scale : -1e30f;
                s[ni][2] = (c     <= r0 + 8) ? s[ni][2] * scale : -1e30f;
                s[ni][3] = (c + 1 <= r0 + 8) ? s[ni][3] * scale : -1e30f;
                mn0 = fmaxf(mn0, fmaxf(s[ni][0], s[ni][1]));
                mn1 = fmaxf(mn1, fmaxf(s[ni][2], s[ni][3]));
            }
            mn0 = fmaxf(mn0, __shfl_xor_sync(0xffffffffu, mn0, 1));
            mn0 = fmaxf(mn0, __shfl_xor_sync(0xffffffffu, mn0, 2));
            mn1 = fmaxf(mn1, __shfl_xor_sync(0xffffffffu, mn1, 1));
            mn1 = fmaxf(mn1, __shfl_xor_sync(0xffffffffu, mn1, 2));

            float mt0 = fmaxf(m0v, mn0), mt1 = fmaxf(m1v, mn1);
            float a0 = __expf(m0v - mt0), a1 = __expf(m1v - mt1);
            m0v = mt0; m1v = mt1;

            // ---- exp (P kept in registers) + row sums ----
            float rs0 = 0.f, rs1 = 0.f;
#pragma unroll
            for (int ni = 0; ni < 8; ni++) {
                s[ni][0] = __expf(s[ni][0] - mt0);
                s[ni][1] = __expf(s[ni][1] - mt0);
                s[ni][2] = __expf(s[ni][2] - mt1);
                s[ni][3] = __expf(s[ni][3] - mt1);
                rs0 += s[ni][0] + s[ni][1];
                rs1 += s[ni][2] + s[ni][3];
            }
            rs0 += __shfl_xor_sync(0xffffffffu, rs0, 1);
            rs0 += __shfl_xor_sync(0xffffffffu, rs0, 2);
            rs1 += __shfl_xor_sync(0xffffffffu, rs1, 1);
            rs1 += __shfl_xor_sync(0xffffffffu, rs1, 2);
            l0 = l0 * a0 + rs0;
            l1 = l1 * a1 + rs1;

#pragma unroll
            for (int ni = 0; ni < 16; ni++) {
                oacc[ni][0] *= a0; oacc[ni][1] *= a0;
                oacc[ni][2] *= a1; oacc[ni][3] *= a1;
            }

            // ---- O += P @ V  (P C-frag == A-frag at k16; V via ldmatrix.trans)
#pragma unroll
            for (int kk2 = 0; kk2 < 4; kk2++) {
                uint32_t af[4];
                af[0] = h2u(s[2 * kk2][0],     s[2 * kk2][1]);
                af[1] = h2u(s[2 * kk2][2],     s[2 * kk2][3]);
                af[2] = h2u(s[2 * kk2 + 1][0], s[2 * kk2 + 1][1]);
                af[3] = h2u(s[2 * kk2 + 1][2], s[2 * kk2 + 1][3]);
#pragma unroll
                for (int nip = 0; nip < 8; nip++) {
                    int row = kk2 * 16 + (lane & 7) + (lane & 8);
                    int c16 = 2 * nip + (lane >> 4);
                    uint32_t r4[4];
                    ldsm4t(r4, Vb + row * 256 + ((c16 ^ (row & 7)) << 4));
                    mma16(oacc[2 * nip],     af, r4[0], r4[1]);
                    mma16(oacc[2 * nip + 1], af, r4[2], r4[3]);
                }
            }
        }
        __syncthreads();
    }

    // ---- epilogue: normalize, write fp16 ao [b*s][h*128+d] ----
    const int b = bh >> 4, h = bh & 15;
    const float inv0 = 1.f / l0, inv1 = 1.f / l1;
#pragma unroll
    for (int ni = 0; ni < 16; ni++) {
        int d = ni * 8 + tg * 2;
        __half* p0 = g_aoh + ((size_t)b * S_LEN + r0) * D_MODEL + h * DHD + d;
        __half* p1 = g_aoh + ((size_t)b * S_LEN + r0 + 8) * D_MODEL + h * DHD + d;
        *(__half2*)p0 = __floats2half2_rn(oacc[ni][0] * inv0, oacc[ni][1] * inv0);
        *(__half2*)p1 = __floats2half2_rn(oacc[ni][2] * inv1, oacc[ni][3] * inv1);
    }
}

// ---------------- launch ----------------------------------------------------
extern "C" void kernel_launch(void* const* d_in, const int* in_sizes, int n_in,
                              void* d_out, int out_size)
{
    (void)in_sizes; (void)n_in; (void)out_size;
    const float* x  = (const float*)d_in[0];
    const float* fc = (const float*)d_in[1];
    const float* fs = (const float*)d_in[2];
    // d_in[3] = mask (causal, analytic)
    const float* wq = (const float*)d_in[4];
    const float* wk = (const float*)d_in[5];
    const float* wv = (const float*)d_in[6];
    const float* wo = (const float*)d_in[7];
    float* out = (float*)d_out;

    cudaFuncSetAttribute(gemm_h_kernel,
                         cudaFuncAttributeMaxDynamicSharedMemorySize, GEMM_SMEM);
    cudaFuncSetAttribute(attn_h_kernel,
                         cudaFuncAttributeMaxDynamicSharedMemorySize, ATT_SMEM);

    // 0) fp32 -> fp16 pre-pass
    dim3 gc(8192, 1, 5);
    cvt_h_kernel<<<gc, 256>>>(x, wq, wk, wv, wo);

    // 1) QKV projections + RoPE
    dim3 g1(D_MODEL / 128, M_ROWS / 128, 3);
    gemm_h_kernel<<<g1, 256, GEMM_SMEM>>>(out, fc, fs, 0);

    // 2) flash attention -> g_aoh
    dim3 g2(S_LEN / 128, NB * NH);
    attn_h_kernel<<<g2, 256, ATT_SMEM>>>();

    // 3) output projection -> d_out (fp32)
    dim3 g3(D_MODEL / 128, M_ROWS / 128, 1);
    gemm_h_kernel<<<g3, 256, GEMM_SMEM>>>(out, fc, fs, 1);
}